// round 14
// baseline (speedup 1.0000x reference)
#include <cuda_runtime.h>
#include <cuda_bf16.h>
#include <cuda_fp16.h>

// Problem constants (fixed-shape problem)
#define MAXN 50176
#define MAXE 800256

// ---------------- scratch ----------------
__device__ __align__(16) __half g_xwh[MAXN * 128]; // xw per node (fp16), layout [node][cc*4+h]
__device__ __align__(16) __half g_idh[MAXN * 128]; // identity (fp16), layout [node][c]
__device__ __align__(16) float g_as[MAXN * 4];
__device__ __align__(16) float g_ad[MAXN * 4];
__device__ __align__(16) int   g_cur[MAXN];
__device__ int   g_off[MAXN + 1];
__device__ int   g_csr[MAXE];
__device__ volatile unsigned long long g_spack[64]; // packed (flag<<32 | aggregate)
__device__ float g_G[128];                          // colsum of tf32(gamma*W_gat)
__device__ float g_B[128];                          // beta @ W_gat
__device__ __align__(16) float g_Bp[256 * 128];     // tf32 fused weights TRANSPOSED: [c][k]

// ---------------- tf32 / mma helpers ----------------
__device__ __forceinline__ unsigned tf32u(float x) {
    unsigned r; asm("cvt.rna.tf32.f32 %0, %1;" : "=r"(r) : "f"(x)); return r;
}
__device__ __forceinline__ void mma1688(float* c, const unsigned* a, const unsigned* b) {
    asm volatile("mma.sync.aligned.m16n8k8.row.col.f32.tf32.tf32.f32 "
        "{%0,%1,%2,%3},{%4,%5,%6,%7},{%8,%9},{%0,%1,%2,%3};"
        : "+f"(c[0]), "+f"(c[1]), "+f"(c[2]), "+f"(c[3])
        : "r"(a[0]), "r"(a[1]), "r"(a[2]), "r"(a[3]), "r"(b[0]), "r"(b[1]));
}
__device__ __forceinline__ void cpa16(unsigned s, const float* g) {
    asm volatile("cp.async.ca.shared.global [%0], [%1], 16;" :: "r"(s), "l"(g));
}

// ---------------- prep (merged): tf32 weights transposed + G/B colsums ----------------
__global__ void prep2_k(const float* __restrict__ gamma, const float* __restrict__ beta,
                        const float* __restrict__ Wgat, const float* __restrict__ Wproj) {
    __shared__ float s1[4], s2[4];
    int c = blockIdx.x, k = threadIdx.x;
    int lane = k & 31, wid = k >> 5;
    float w;
    if (c < 128) w = gamma[k] * Wgat[k * 128 + c];
    else         w = Wproj[k * 128 + (c - 128)];
    float wr = __uint_as_float(tf32u(w));
    g_Bp[c * 128 + k] = wr;
    if (c < 128) {
        float sw = wr;
        float sb = beta[k] * Wgat[k * 128 + c];
        #pragma unroll
        for (int o = 16; o > 0; o >>= 1) {
            sw += __shfl_xor_sync(0xFFFFFFFFu, sw, o);
            sb += __shfl_xor_sync(0xFFFFFFFFu, sb, o);
        }
        if (lane == 0) { s1[wid] = sw; s2[wid] = sb; }
        __syncthreads();
        if (k == 0) {
            g_G[c] = s1[0] + s1[1] + s1[2] + s1[3];
            g_B[c] = s2[0] + s2[1] + s2[2] + s2[3];
        }
    }
}

// ---------------- CSR build ----------------
__global__ void hist_k(const int* __restrict__ dst, int e) {
    if (blockIdx.x == 0 && threadIdx.x < 64) g_spack[threadIdx.x] = 0ull;
    int i = blockIdx.x * blockDim.x + threadIdx.x;
    if (i < e) atomicAdd(&g_cur[dst[i]], 1);
}

// Single-pass scan with decoupled lookback.
#define SCB 1024
__global__ void scan1_k(int n) {
    __shared__ int wsum[8];
    __shared__ int s_off;
    int b = blockIdx.x, tid = threadIdx.x, lane = tid & 31, wid = tid >> 5;
    int base = b * SCB + tid * 4;
    int4 v = make_int4(0, 0, 0, 0);
    if (base + 3 < n)      v = *(const int4*)&g_cur[base];
    else {
        if (base     < n) v.x = g_cur[base];
        if (base + 1 < n) v.y = g_cur[base + 1];
        if (base + 2 < n) v.z = g_cur[base + 2];
    }
    int tsum = v.x + v.y + v.z + v.w;
    int inc = tsum;
    #pragma unroll
    for (int o = 1; o < 32; o <<= 1) {
        int t = __shfl_up_sync(0xFFFFFFFFu, inc, o);
        if (lane >= o) inc += t;
    }
    if (lane == 31) wsum[wid] = inc;
    __syncthreads();

    if (tid == 0) {
        int tot = wsum[0] + wsum[1] + wsum[2] + wsum[3]
                + wsum[4] + wsum[5] + wsum[6] + wsum[7];
        g_spack[b] = (1ull << 32) | (unsigned)tot;
    }
    if (wid == 0 && lane < 8) {
        int wv = wsum[lane];
        int wi = wv;
        #pragma unroll
        for (int o = 1; o < 8; o <<= 1) {
            int t = __shfl_up_sync(0xFFu, wi, o);
            if (lane >= o) wi += t;
        }
        wsum[lane] = wi - wv;
    }
    if (wid == 1) {
        int acc = 0;
        for (int p = lane; p < b; p += 32) {
            unsigned long long pk;
            do { pk = g_spack[p]; } while (pk == 0ull);
            acc += (int)(unsigned)pk;
        }
        #pragma unroll
        for (int o = 16; o > 0; o >>= 1) acc += __shfl_xor_sync(0xFFFFFFFFu, acc, o);
        if (lane == 0) s_off = acc;
    }
    __syncthreads();

    int e0 = inc - tsum + wsum[wid] + s_off;
    int e1 = e0 + v.x, e2 = e1 + v.y, e3 = e2 + v.z, e4 = e3 + v.w;
    if (base     < n) { g_cur[base]     = e0; g_off[base + 1] = e1; }
    if (base + 1 < n) { g_cur[base + 1] = e1; g_off[base + 2] = e2; }
    if (base + 2 < n) { g_cur[base + 2] = e2; g_off[base + 3] = e3; }
    if (base + 3 < n) { g_cur[base + 3] = e3; g_off[base + 4] = e4; }
    if (b == 0 && tid == 0) g_off[0] = 0;
}

__global__ void scat_k(const int* __restrict__ src, const int* __restrict__ dst, int e) {
    int i = blockIdx.x * blockDim.x + threadIdx.x;
    if (i < e) {
        int p = atomicAdd(&g_cur[dst[i]], 1);
        g_csr[p] = src[i];
    }
}

// ---------------- node kernel: LN + dual GEMM (tf32, vectorized frags) + attn dots ----
#define TMM 64
#define APITCH 132
#define BKP 36
#define SM_AS 0
#define SM_BF (TMM * APITCH)                 // 8448
#define BKBUF (256 * BKP)                    // 9216
#define SM_MU (SM_BF + 2 * BKBUF)            // 26880
#define SM_RS (SM_MU + TMM)
#define SM_ATT (SM_RS + TMM)
#define SM_G  (SM_ATT + 256)
#define SM_BB (SM_G + 128)
#define SM_BP (SM_BB + 128)
#define NODE2_FLOATS (SM_BP + 128)
#define NODE2_BYTES (NODE2_FLOATS * 4)       // 110592 B

__global__ void __launch_bounds__(256, 2) node_k(
    const float* __restrict__ x, const float* __restrict__ att_src,
    const float* __restrict__ att_dst, const float* __restrict__ bproj, int n)
{
    extern __shared__ float sm[];
    int tid = threadIdx.x;
    int wid = tid >> 5, lane = tid & 31;
    int g = lane >> 2, tig = lane & 3;
    int i0 = blockIdx.x * TMM;
    unsigned smbase = (unsigned)__cvta_generic_to_shared(sm);

    if (tid < 128) {
        sm[SM_ATT + tid]       = att_src[tid];
        sm[SM_ATT + 128 + tid] = att_dst[tid];
        sm[SM_G + tid]  = g_G[tid];
        sm[SM_BB + tid] = g_B[tid];
        sm[SM_BP + tid] = bproj[tid];
    }

    auto loadB = [&](int kc, int buf) {
        const float* gp = g_Bp + kc * 32;
        unsigned bs = smbase + (SM_BF + buf * BKBUF) * 4;
        #pragma unroll
        for (int u = 0; u < 8; u++) {
            int idx = u * 256 + tid;
            int c = idx >> 3, q = idx & 7;
            cpa16(bs + (c * BKP + q * 4) * 4, gp + c * 128 + q * 4);
        }
        asm volatile("cp.async.commit_group;");
    };
    loadB(0, 0);

    for (int rr = 0; rr < TMM / 8; rr++) {
        int r = wid * (TMM / 8) + rr;
        int node = i0 + r;
        float4 v = make_float4(0.f, 0.f, 0.f, 0.f);
        if (node < n) v = *(const float4*)&x[(long)node * 128 + lane * 4];
        float s = v.x + v.y + v.z + v.w;
        float q = v.x * v.x + v.y * v.y + v.z * v.z + v.w * v.w;
        #pragma unroll
        for (int o = 16; o > 0; o >>= 1) {
            s += __shfl_xor_sync(0xFFFFFFFFu, s, o);
            q += __shfl_xor_sync(0xFFFFFFFFu, q, o);
        }
        float mu = s * (1.f / 128.f);
        float var = q * (1.f / 128.f) - mu * mu;
        if (lane == 0) { sm[SM_MU + r] = mu; sm[SM_RS + r] = rsqrtf(var + 1e-5f); }
        float4 t;
        t.x = __uint_as_float(tf32u(v.x));
        t.y = __uint_as_float(tf32u(v.y));
        t.z = __uint_as_float(tf32u(v.z));
        t.w = __uint_as_float(tf32u(v.w));
        *(float4*)&sm[SM_AS + r * APITCH + lane * 4] = t;
    }

    float c[4][4][4];
    #pragma unroll
    for (int a = 0; a < 4; a++)
        #pragma unroll
        for (int b = 0; b < 4; b++)
            #pragma unroll
            for (int d = 0; d < 4; d++) c[a][b][d] = 0.f;

    int colb = wid * 32;

    for (int kc = 0; kc < 4; kc++) {
        if (kc) __syncthreads();
        if (kc < 3) loadB(kc + 1, (kc + 1) & 1);
        if (kc < 3) asm volatile("cp.async.wait_group 1;");
        else        asm volatile("cp.async.wait_group 0;");
        __syncthreads();

        const float* Bh = &sm[SM_BF + (kc & 1) * BKBUF];

        float4 bf[4][2];
        #pragma unroll
        for (int ni = 0; ni < 4; ni++) {
            int col = colb + ni * 8 + g;
            const float* bp = &Bh[col * BKP + tig * 8];
            bf[ni][0] = *(const float4*)bp;
            bf[ni][1] = *(const float4*)(bp + 4);
        }

        #pragma unroll
        for (int mi = 0; mi < 4; mi++) {
            const float* Ar = &sm[SM_AS + (mi * 16 + g) * APITCH + kc * 32 + tig * 8];
            const float* Ar8 = Ar + 8 * APITCH;
            float4 a0 = *(const float4*)Ar;
            float4 a1 = *(const float4*)(Ar + 4);
            float4 e0 = *(const float4*)Ar8;
            float4 e1 = *(const float4*)(Ar8 + 4);
            unsigned a[4]; unsigned b[2];
            a[0] = __float_as_uint(a0.x); a[1] = __float_as_uint(e0.x);
            a[2] = __float_as_uint(a0.y); a[3] = __float_as_uint(e0.y);
            #pragma unroll
            for (int ni = 0; ni < 4; ni++) {
                b[0] = __float_as_uint(bf[ni][0].x); b[1] = __float_as_uint(bf[ni][0].y);
                mma1688(c[mi][ni], a, b);
            }
            a[0] = __float_as_uint(a0.z); a[1] = __float_as_uint(e0.z);
            a[2] = __float_as_uint(a0.w); a[3] = __float_as_uint(e0.w);
            #pragma unroll
            for (int ni = 0; ni < 4; ni++) {
                b[0] = __float_as_uint(bf[ni][0].z); b[1] = __float_as_uint(bf[ni][0].w);
                mma1688(c[mi][ni], a, b);
            }
            a[0] = __float_as_uint(a1.x); a[1] = __float_as_uint(e1.x);
            a[2] = __float_as_uint(a1.y); a[3] = __float_as_uint(e1.y);
            #pragma unroll
            for (int ni = 0; ni < 4; ni++) {
                b[0] = __float_as_uint(bf[ni][1].x); b[1] = __float_as_uint(bf[ni][1].y);
                mma1688(c[mi][ni], a, b);
            }
            a[0] = __float_as_uint(a1.z); a[1] = __float_as_uint(e1.z);
            a[2] = __float_as_uint(a1.w); a[3] = __float_as_uint(e1.w);
            #pragma unroll
            for (int ni = 0; ni < 4; ni++) {
                b[0] = __float_as_uint(bf[ni][1].z); b[1] = __float_as_uint(bf[ni][1].w);
                mma1688(c[mi][ni], a, b);
            }
        }
    }

    // Epilogue
    if (wid < 4) {
        int h = wid;
        #pragma unroll
        for (int mi = 0; mi < 4; mi++) {
            #pragma unroll
            for (int hf = 0; hf < 2; hf++) {
                int r = mi * 16 + g + hf * 8;
                int node = i0 + r;
                float mu = sm[SM_MU + r], rs = sm[SM_RS + r];
                float ps = 0.f, pd = 0.f;
                #pragma unroll
                for (int ni = 0; ni < 4; ni++) {
                    #pragma unroll
                    for (int j = 0; j < 2; j++) {
                        int cl = ni * 8 + 2 * tig + j;
                        int cg = colb + cl;
                        float acc = c[mi][ni][hf * 2 + j];
                        float val = rs * (acc - mu * sm[SM_G + cg]) + sm[SM_BB + cg];
                        ps += val * sm[SM_ATT + cg];
                        pd += val * sm[SM_ATT + 128 + cg];
                        if (node < n)
                            g_xwh[(long)node * 128 + cl * 4 + h] = __float2half_rn(val);
                    }
                }
                ps += __shfl_xor_sync(0xFFFFFFFFu, ps, 1);
                ps += __shfl_xor_sync(0xFFFFFFFFu, ps, 2);
                pd += __shfl_xor_sync(0xFFFFFFFFu, pd, 1);
                pd += __shfl_xor_sync(0xFFFFFFFFu, pd, 2);
                if (tig == 0 && node < n) {
                    g_as[node * 4 + h] = ps;
                    g_ad[node * 4 + h] = pd;
                }
            }
        }
    } else {
        #pragma unroll
        for (int mi = 0; mi < 4; mi++) {
            #pragma unroll
            for (int hf = 0; hf < 2; hf++) {
                int r = mi * 16 + g + hf * 8;
                int node = i0 + r;
                if (node >= n) continue;
                #pragma unroll
                for (int ni = 0; ni < 4; ni++) {
                    int cid0 = (wid - 4) * 32 + ni * 8 + 2 * tig;
                    float v0 = c[mi][ni][hf * 2 + 0] + sm[SM_BP + cid0];
                    float v1 = c[mi][ni][hf * 2 + 1] + sm[SM_BP + cid0 + 1];
                    *(__half2*)&g_idh[(long)node * 128 + cid0] = __floats2half2_rn(v0, v1);
                }
            }
        }
    }
}

// ---------------- gather: 2 warps per node, chunked softmax aggregate (fp16 values) ----
__device__ __forceinline__ float lrelu(float z) { return z > 0.f ? z : 0.2f * z; }

__device__ __forceinline__ float4 ldxw_h(long idx128, int lane) {
    const __half* p = g_xwh + idx128 + lane * 4;
    uint2 u = *(const uint2*)p;
    __half2 h0 = *reinterpret_cast<__half2*>(&u.x);
    __half2 h1 = *reinterpret_cast<__half2*>(&u.y);
    float2 f0 = __half22float2(h0);
    float2 f1 = __half22float2(h1);
    return make_float4(f0.x, f0.y, f1.x, f1.y);
}

// Block = 256 threads = 8 warps = 4 nodes (2 warps per node).
// Even warp (sub=0): self-loop + chunks 0,2,4,... ; odd warp: chunks 1,3,5,...
// Partials combined via smem; epilogue on even warp.
__global__ void __launch_bounds__(256) gather_k(const float* __restrict__ bias,
                                                float* __restrict__ out, int n)
{
    __shared__ float4 sq[8][32];
    __shared__ int    ss[8][32];
    __shared__ float4 sd[4][32];
    __shared__ float4 sa[4][32];
    int w = threadIdx.x >> 5;
    int lane = threadIdx.x & 31;
    int nid = w >> 1;
    int sub = w & 1;
    int i = blockIdx.x * 4 + nid;
    bool valid = (i < n);

    float4 ad = make_float4(0.f, 0.f, 0.f, 0.f);
    int beg = 0, end = 0;
    long myb = 0;
    float d0 = 0.f, d1 = 0.f, d2 = 0.f, d3 = 0.f;
    float a0 = 0.f, a1 = 0.f, a2 = 0.f, a3 = 0.f;

    if (valid) {
        ad = *(const float4*)&g_ad[i * 4];
        beg = g_off[i];
        end = g_off[i + 1];
        myb = (long)i * 128;
        if (sub == 0) {
            float4 asi = *(const float4*)&g_as[i * 4];
            float4 xv = ldxw_h(myb, lane);
            float p0 = __expf(lrelu(asi.x + ad.x));
            float p1 = __expf(lrelu(asi.y + ad.y));
            float p2 = __expf(lrelu(asi.z + ad.z));
            float p3 = __expf(lrelu(asi.w + ad.w));
            d0 = p0; d1 = p1; d2 = p2; d3 = p3;
            a0 = p0 * xv.x; a1 = p1 * xv.y; a2 = p2 * xv.z; a3 = p3 * xv.w;
        }
    }

    if (valid) {
        for (int cs = beg + sub * 32; cs < end; cs += 64) {
            int cnt = min(32, end - cs);
            int j = cs + lane;
            if (lane < cnt) {
                int s = __ldg(&g_csr[j]);
                float4 a4 = *(const float4*)&g_as[s * 4];
                float4 q;
                q.x = __expf(lrelu(a4.x + ad.x));
                q.y = __expf(lrelu(a4.y + ad.y));
                q.z = __expf(lrelu(a4.z + ad.z));
                q.w = __expf(lrelu(a4.w + ad.w));
                ss[w][lane] = s;
                sq[w][lane] = q;
            }
            __syncwarp();
            #pragma unroll 4
            for (int t = 0; t < cnt; t++) {
                int st = ss[w][t];
                float4 qt = sq[w][t];
                float4 x4 = ldxw_h((long)st * 128, lane);
                d0 += qt.x; a0 = fmaf(qt.x, x4.x, a0);
                d1 += qt.y; a1 = fmaf(qt.y, x4.y, a1);
                d2 += qt.z; a2 = fmaf(qt.z, x4.z, a2);
                d3 += qt.w; a3 = fmaf(qt.w, x4.w, a3);
            }
            __syncwarp();
        }
    }

    // combine partials: odd warp publishes, even warp reduces + epilogue
    if (sub == 1) {
        sd[nid][lane] = make_float4(d0, d1, d2, d3);
        sa[nid][lane] = make_float4(a0, a1, a2, a3);
    }
    __syncthreads();
    if (sub == 0 && valid) {
        float4 dd = sd[nid][lane];
        float4 aa = sa[nid][lane];
        d0 += dd.x; d1 += dd.y; d2 += dd.z; d3 += dd.w;
        a0 += aa.x; a1 += aa.y; a2 += aa.z; a3 += aa.w;

        float r0 = a0 / (d0 + 1e-16f);
        float r1 = a1 / (d1 + 1e-16f);
        float r2 = a2 / (d2 + 1e-16f);
        float r3 = a3 / (d3 + 1e-16f);

        long ob = myb + lane;
        out[ob +  0] = fmaxf(__half2float(g_idh[ob +  0]) + r0 + __ldg(&bias[lane +  0]), 0.f);
        out[ob + 32] = fmaxf(__half2float(g_idh[ob + 32]) + r1 + __ldg(&bias[lane + 32]), 0.f);
        out[ob + 64] = fmaxf(__half2float(g_idh[ob + 64]) + r2 + __ldg(&bias[lane + 64]), 0.f);
        out[ob + 96] = fmaxf(__half2float(g_idh[ob + 96]) + r3 + __ldg(&bias[lane + 96]), 0.f);
    }
}

// ---------------- launch ----------------
extern "C" void kernel_launch(void* const* d_in, const int* in_sizes, int n_in,
                              void* d_out, int out_size)
{
    const float* x        = (const float*)d_in[0];
    const int*   ei       = (const int*)d_in[1];
    const float* gamma    = (const float*)d_in[2];
    const float* beta     = (const float*)d_in[3];
    const float* Wgat     = (const float*)d_in[4];
    const float* att_src  = (const float*)d_in[5];
    const float* att_dst  = (const float*)d_in[6];
    const float* bias_gat = (const float*)d_in[7];
    const float* Wproj    = (const float*)d_in[8];
    const float* bproj    = (const float*)d_in[9];

    int n = in_sizes[0] / 128;
    int e = in_sizes[1] / 2;
    const int* src = ei;
    const int* dst = ei + e;
    int nb = (n + SCB - 1) / SCB;

    void* curp = nullptr;
    cudaGetSymbolAddress(&curp, g_cur);

    cudaFuncSetAttribute(node_k, cudaFuncAttributeMaxDynamicSharedMemorySize, NODE2_BYTES);

    cudaStream_t s2;
    cudaStreamCreate(&s2);
    cudaEvent_t evFork, evJoin;
    cudaEventCreateWithFlags(&evFork, cudaEventDisableTiming);
    cudaEventCreateWithFlags(&evJoin, cudaEventDisableTiming);

    cudaEventRecord(evFork, 0);
    cudaStreamWaitEvent(s2, evFork, 0);

    // side stream: CSR build
    cudaMemsetAsync(curp, 0, n * sizeof(int), s2);
    hist_k<<<(e + 255) / 256, 256, 0, s2>>>(dst, e);
    scan1_k<<<nb, 256, 0, s2>>>(n);
    scat_k<<<(e + 255) / 256, 256, 0, s2>>>(src, dst, e);
    cudaEventRecord(evJoin, s2);

    // main stream: GEMM path
    prep2_k<<<256, 128>>>(gamma, beta, Wgat, Wproj);
    node_k<<<(n + TMM - 1) / TMM, 256, NODE2_BYTES>>>(x, att_src, att_dst, bproj, n);

    cudaStreamWaitEvent(0, evJoin, 0);
    gather_k<<<(n + 3) / 4, 256>>>(bias_gat, (float*)d_out, n);

    cudaEventDestroy(evFork);
    cudaEventDestroy(evJoin);
    cudaStreamDestroy(s2);
}

// round 15
// speedup vs baseline: 1.2230x; 1.2230x over previous
#include <cuda_runtime.h>
#include <cuda_bf16.h>
#include <cuda_fp16.h>

// Problem constants (fixed-shape problem)
#define MAXN 50176
#define MAXE 800256

// ---------------- scratch ----------------
__device__ __align__(16) __half g_xwh[MAXN * 128]; // xw per node (fp16), layout [node][cc*4+h]
__device__ __align__(16) __half g_idh[MAXN * 128]; // identity (fp16), layout [node][c]
__device__ __align__(16) float g_as[MAXN * 4];
__device__ __align__(16) float g_ad[MAXN * 4];
__device__ __align__(16) int   g_cur[MAXN];        // zero-init at load; gather re-zeros per replay
__device__ int   g_off[MAXN + 1];
__device__ int   g_csr[MAXE];
__device__ volatile unsigned long long g_spack[64]; // packed (flag<<32 | aggregate)
__device__ float g_G[128];                          // colsum of tf32(gamma*W_gat)
__device__ float g_B[128];                          // beta @ W_gat
__device__ __align__(16) float g_Bp[256 * 128];     // tf32 fused weights TRANSPOSED: [c][k]

// ---------------- tf32 / mma helpers ----------------
__device__ __forceinline__ unsigned tf32u(float x) {
    unsigned r; asm("cvt.rna.tf32.f32 %0, %1;" : "=r"(r) : "f"(x)); return r;
}
__device__ __forceinline__ void mma1688(float* c, const unsigned* a, const unsigned* b) {
    asm volatile("mma.sync.aligned.m16n8k8.row.col.f32.tf32.tf32.f32 "
        "{%0,%1,%2,%3},{%4,%5,%6,%7},{%8,%9},{%0,%1,%2,%3};"
        : "+f"(c[0]), "+f"(c[1]), "+f"(c[2]), "+f"(c[3])
        : "r"(a[0]), "r"(a[1]), "r"(a[2]), "r"(a[3]), "r"(b[0]), "r"(b[1]));
}
__device__ __forceinline__ void cpa16(unsigned s, const float* g) {
    asm volatile("cp.async.ca.shared.global [%0], [%1], 16;" :: "r"(s), "l"(g));
}

// ---------------- prep (merged): tf32 weights transposed + G/B colsums ----------------
__global__ void prep2_k(const float* __restrict__ gamma, const float* __restrict__ beta,
                        const float* __restrict__ Wgat, const float* __restrict__ Wproj) {
    __shared__ float s1[4], s2[4];
    int c = blockIdx.x, k = threadIdx.x;
    int lane = k & 31, wid = k >> 5;
    float w;
    if (c < 128) w = gamma[k] * Wgat[k * 128 + c];
    else         w = Wproj[k * 128 + (c - 128)];
    float wr = __uint_as_float(tf32u(w));
    g_Bp[c * 128 + k] = wr;
    if (c < 128) {
        float sw = wr;
        float sb = beta[k] * Wgat[k * 128 + c];
        #pragma unroll
        for (int o = 16; o > 0; o >>= 1) {
            sw += __shfl_xor_sync(0xFFFFFFFFu, sw, o);
            sb += __shfl_xor_sync(0xFFFFFFFFu, sb, o);
        }
        if (lane == 0) { s1[wid] = sw; s2[wid] = sb; }
        __syncthreads();
        if (k == 0) {
            g_G[c] = s1[0] + s1[1] + s1[2] + s1[3];
            g_B[c] = s2[0] + s2[1] + s2[2] + s2[3];
        }
    }
}

// ---------------- CSR build ----------------
__global__ void hist_k(const int* __restrict__ dst, int e) {
    if (blockIdx.x == 0 && threadIdx.x < 64) g_spack[threadIdx.x] = 0ull;
    int i = blockIdx.x * blockDim.x + threadIdx.x;
    if (i < e) atomicAdd(&g_cur[dst[i]], 1);
}

// Single-pass scan with decoupled lookback.
#define SCB 1024
__global__ void scan1_k(int n) {
    __shared__ int wsum[8];
    __shared__ int s_off;
    int b = blockIdx.x, tid = threadIdx.x, lane = tid & 31, wid = tid >> 5;
    int base = b * SCB + tid * 4;
    int4 v = make_int4(0, 0, 0, 0);
    if (base + 3 < n)      v = *(const int4*)&g_cur[base];
    else {
        if (base     < n) v.x = g_cur[base];
        if (base + 1 < n) v.y = g_cur[base + 1];
        if (base + 2 < n) v.z = g_cur[base + 2];
    }
    int tsum = v.x + v.y + v.z + v.w;
    int inc = tsum;
    #pragma unroll
    for (int o = 1; o < 32; o <<= 1) {
        int t = __shfl_up_sync(0xFFFFFFFFu, inc, o);
        if (lane >= o) inc += t;
    }
    if (lane == 31) wsum[wid] = inc;
    __syncthreads();

    if (tid == 0) {
        int tot = wsum[0] + wsum[1] + wsum[2] + wsum[3]
                + wsum[4] + wsum[5] + wsum[6] + wsum[7];
        g_spack[b] = (1ull << 32) | (unsigned)tot;
    }
    if (wid == 0 && lane < 8) {
        int wv = wsum[lane];
        int wi = wv;
        #pragma unroll
        for (int o = 1; o < 8; o <<= 1) {
            int t = __shfl_up_sync(0xFFu, wi, o);
            if (lane >= o) wi += t;
        }
        wsum[lane] = wi - wv;
    }
    if (wid == 1) {
        int acc = 0;
        for (int p = lane; p < b; p += 32) {
            unsigned long long pk;
            do { pk = g_spack[p]; } while (pk == 0ull);
            acc += (int)(unsigned)pk;
        }
        #pragma unroll
        for (int o = 16; o > 0; o >>= 1) acc += __shfl_xor_sync(0xFFFFFFFFu, acc, o);
        if (lane == 0) s_off = acc;
    }
    __syncthreads();

    int e0 = inc - tsum + wsum[wid] + s_off;
    int e1 = e0 + v.x, e2 = e1 + v.y, e3 = e2 + v.z, e4 = e3 + v.w;
    if (base     < n) { g_cur[base]     = e0; g_off[base + 1] = e1; }
    if (base + 1 < n) { g_cur[base + 1] = e1; g_off[base + 2] = e2; }
    if (base + 2 < n) { g_cur[base + 2] = e2; g_off[base + 3] = e3; }
    if (base + 3 < n) { g_cur[base + 3] = e3; g_off[base + 4] = e4; }
    if (b == 0 && tid == 0) g_off[0] = 0;
}

__global__ void scat_k(const int* __restrict__ src, const int* __restrict__ dst, int e) {
    int i = blockIdx.x * blockDim.x + threadIdx.x;
    if (i < e) {
        int p = atomicAdd(&g_cur[dst[i]], 1);
        g_csr[p] = src[i];
    }
}

// ---------------- node kernel: LN + dual GEMM (tf32, vectorized frags) + attn dots ----
#define TMM 64
#define APITCH 132
#define BKP 36
#define SM_AS 0
#define SM_BF (TMM * APITCH)                 // 8448
#define BKBUF (256 * BKP)                    // 9216
#define SM_MU (SM_BF + 2 * BKBUF)            // 26880
#define SM_RS (SM_MU + TMM)
#define SM_ATT (SM_RS + TMM)
#define SM_G  (SM_ATT + 256)
#define SM_BB (SM_G + 128)
#define SM_BP (SM_BB + 128)
#define NODE2_FLOATS (SM_BP + 128)
#define NODE2_BYTES (NODE2_FLOATS * 4)       // 110592 B

__global__ void __launch_bounds__(256, 2) node_k(
    const float* __restrict__ x, const float* __restrict__ att_src,
    const float* __restrict__ att_dst, const float* __restrict__ bproj, int n)
{
    extern __shared__ float sm[];
    int tid = threadIdx.x;
    int wid = tid >> 5, lane = tid & 31;
    int g = lane >> 2, tig = lane & 3;
    int i0 = blockIdx.x * TMM;
    unsigned smbase = (unsigned)__cvta_generic_to_shared(sm);

    if (tid < 128) {
        sm[SM_ATT + tid]       = att_src[tid];
        sm[SM_ATT + 128 + tid] = att_dst[tid];
        sm[SM_G + tid]  = g_G[tid];
        sm[SM_BB + tid] = g_B[tid];
        sm[SM_BP + tid] = bproj[tid];
    }

    auto loadB = [&](int kc, int buf) {
        const float* gp = g_Bp + kc * 32;
        unsigned bs = smbase + (SM_BF + buf * BKBUF) * 4;
        #pragma unroll
        for (int u = 0; u < 8; u++) {
            int idx = u * 256 + tid;
            int c = idx >> 3, q = idx & 7;
            cpa16(bs + (c * BKP + q * 4) * 4, gp + c * 128 + q * 4);
        }
        asm volatile("cp.async.commit_group;");
    };
    loadB(0, 0);

    for (int rr = 0; rr < TMM / 8; rr++) {
        int r = wid * (TMM / 8) + rr;
        int node = i0 + r;
        float4 v = make_float4(0.f, 0.f, 0.f, 0.f);
        if (node < n) v = *(const float4*)&x[(long)node * 128 + lane * 4];
        float s = v.x + v.y + v.z + v.w;
        float q = v.x * v.x + v.y * v.y + v.z * v.z + v.w * v.w;
        #pragma unroll
        for (int o = 16; o > 0; o >>= 1) {
            s += __shfl_xor_sync(0xFFFFFFFFu, s, o);
            q += __shfl_xor_sync(0xFFFFFFFFu, q, o);
        }
        float mu = s * (1.f / 128.f);
        float var = q * (1.f / 128.f) - mu * mu;
        if (lane == 0) { sm[SM_MU + r] = mu; sm[SM_RS + r] = rsqrtf(var + 1e-5f); }
        float4 t;
        t.x = __uint_as_float(tf32u(v.x));
        t.y = __uint_as_float(tf32u(v.y));
        t.z = __uint_as_float(tf32u(v.z));
        t.w = __uint_as_float(tf32u(v.w));
        *(float4*)&sm[SM_AS + r * APITCH + lane * 4] = t;
    }

    float c[4][4][4];
    #pragma unroll
    for (int a = 0; a < 4; a++)
        #pragma unroll
        for (int b = 0; b < 4; b++)
            #pragma unroll
            for (int d = 0; d < 4; d++) c[a][b][d] = 0.f;

    int colb = wid * 32;

    for (int kc = 0; kc < 4; kc++) {
        if (kc) __syncthreads();
        if (kc < 3) loadB(kc + 1, (kc + 1) & 1);
        if (kc < 3) asm volatile("cp.async.wait_group 1;");
        else        asm volatile("cp.async.wait_group 0;");
        __syncthreads();

        const float* Bh = &sm[SM_BF + (kc & 1) * BKBUF];

        float4 bf[4][2];
        #pragma unroll
        for (int ni = 0; ni < 4; ni++) {
            int col = colb + ni * 8 + g;
            const float* bp = &Bh[col * BKP + tig * 8];
            bf[ni][0] = *(const float4*)bp;
            bf[ni][1] = *(const float4*)(bp + 4);
        }

        #pragma unroll
        for (int mi = 0; mi < 4; mi++) {
            const float* Ar = &sm[SM_AS + (mi * 16 + g) * APITCH + kc * 32 + tig * 8];
            const float* Ar8 = Ar + 8 * APITCH;
            float4 a0 = *(const float4*)Ar;
            float4 a1 = *(const float4*)(Ar + 4);
            float4 e0 = *(const float4*)Ar8;
            float4 e1 = *(const float4*)(Ar8 + 4);
            unsigned a[4]; unsigned b[2];
            a[0] = __float_as_uint(a0.x); a[1] = __float_as_uint(e0.x);
            a[2] = __float_as_uint(a0.y); a[3] = __float_as_uint(e0.y);
            #pragma unroll
            for (int ni = 0; ni < 4; ni++) {
                b[0] = __float_as_uint(bf[ni][0].x); b[1] = __float_as_uint(bf[ni][0].y);
                mma1688(c[mi][ni], a, b);
            }
            a[0] = __float_as_uint(a0.z); a[1] = __float_as_uint(e0.z);
            a[2] = __float_as_uint(a0.w); a[3] = __float_as_uint(e0.w);
            #pragma unroll
            for (int ni = 0; ni < 4; ni++) {
                b[0] = __float_as_uint(bf[ni][0].z); b[1] = __float_as_uint(bf[ni][0].w);
                mma1688(c[mi][ni], a, b);
            }
            a[0] = __float_as_uint(a1.x); a[1] = __float_as_uint(e1.x);
            a[2] = __float_as_uint(a1.y); a[3] = __float_as_uint(e1.y);
            #pragma unroll
            for (int ni = 0; ni < 4; ni++) {
                b[0] = __float_as_uint(bf[ni][1].x); b[1] = __float_as_uint(bf[ni][1].y);
                mma1688(c[mi][ni], a, b);
            }
            a[0] = __float_as_uint(a1.z); a[1] = __float_as_uint(e1.z);
            a[2] = __float_as_uint(a1.w); a[3] = __float_as_uint(e1.w);
            #pragma unroll
            for (int ni = 0; ni < 4; ni++) {
                b[0] = __float_as_uint(bf[ni][1].z); b[1] = __float_as_uint(bf[ni][1].w);
                mma1688(c[mi][ni], a, b);
            }
        }
    }

    // Epilogue
    if (wid < 4) {
        int h = wid;
        #pragma unroll
        for (int mi = 0; mi < 4; mi++) {
            #pragma unroll
            for (int hf = 0; hf < 2; hf++) {
                int r = mi * 16 + g + hf * 8;
                int node = i0 + r;
                float mu = sm[SM_MU + r], rs = sm[SM_RS + r];
                float ps = 0.f, pd = 0.f;
                #pragma unroll
                for (int ni = 0; ni < 4; ni++) {
                    #pragma unroll
                    for (int j = 0; j < 2; j++) {
                        int cl = ni * 8 + 2 * tig + j;
                        int cg = colb + cl;
                        float acc = c[mi][ni][hf * 2 + j];
                        float val = rs * (acc - mu * sm[SM_G + cg]) + sm[SM_BB + cg];
                        ps += val * sm[SM_ATT + cg];
                        pd += val * sm[SM_ATT + 128 + cg];
                        if (node < n)
                            g_xwh[(long)node * 128 + cl * 4 + h] = __float2half_rn(val);
                    }
                }
                ps += __shfl_xor_sync(0xFFFFFFFFu, ps, 1);
                ps += __shfl_xor_sync(0xFFFFFFFFu, ps, 2);
                pd += __shfl_xor_sync(0xFFFFFFFFu, pd, 1);
                pd += __shfl_xor_sync(0xFFFFFFFFu, pd, 2);
                if (tig == 0 && node < n) {
                    g_as[node * 4 + h] = ps;
                    g_ad[node * 4 + h] = pd;
                }
            }
        }
    } else {
        #pragma unroll
        for (int mi = 0; mi < 4; mi++) {
            #pragma unroll
            for (int hf = 0; hf < 2; hf++) {
                int r = mi * 16 + g + hf * 8;
                int node = i0 + r;
                if (node >= n) continue;
                #pragma unroll
                for (int ni = 0; ni < 4; ni++) {
                    int cid0 = (wid - 4) * 32 + ni * 8 + 2 * tig;
                    float v0 = c[mi][ni][hf * 2 + 0] + sm[SM_BP + cid0];
                    float v1 = c[mi][ni][hf * 2 + 1] + sm[SM_BP + cid0 + 1];
                    *(__half2*)&g_idh[(long)node * 128 + cid0] = __floats2half2_rn(v0, v1);
                }
            }
        }
    }
}

// ---------------- gather: 1 warp per node (R11 form) + epilogue prefetch ----------------
__device__ __forceinline__ float lrelu(float z) { return z > 0.f ? z : 0.2f * z; }

__device__ __forceinline__ float4 ldxw_h(long idx128, int lane) {
    const __half* p = g_xwh + idx128 + lane * 4;
    uint2 u = *(const uint2*)p;
    __half2 h0 = *reinterpret_cast<__half2*>(&u.x);
    __half2 h1 = *reinterpret_cast<__half2*>(&u.y);
    float2 f0 = __half22float2(h0);
    float2 f1 = __half22float2(h1);
    return make_float4(f0.x, f0.y, f1.x, f1.y);
}

__global__ void __launch_bounds__(256) gather_k(const float* __restrict__ bias,
                                                float* __restrict__ out, int n)
{
    __shared__ float4 sq[8][32];
    __shared__ int    ss[8][32];
    int w = threadIdx.x >> 5;
    int lane = threadIdx.x & 31;
    int i = (blockIdx.x * 256 + threadIdx.x) >> 5;
    if (i >= n) return;

    float4 ad  = *(const float4*)&g_ad[i * 4];
    float4 asi = *(const float4*)&g_as[i * 4];
    int beg = g_off[i], end = g_off[i + 1];
    long myb = (long)i * 128;

    // restore g_cur to zero for the next replay's hist_k (g_cur unused here)
    if (lane == 0) g_cur[i] = 0;

    // prefetch epilogue operands (addresses known up-front)
    long ob = myb + lane;
    float id0 = __half2float(g_idh[ob +  0]);
    float id1 = __half2float(g_idh[ob + 32]);
    float id2 = __half2float(g_idh[ob + 64]);
    float id3 = __half2float(g_idh[ob + 96]);
    float b0 = __ldg(&bias[lane +  0]);
    float b1 = __ldg(&bias[lane + 32]);
    float b2 = __ldg(&bias[lane + 64]);
    float b3 = __ldg(&bias[lane + 96]);

    float4 xv = ldxw_h(myb, lane);

    float p0 = __expf(lrelu(asi.x + ad.x));
    float p1 = __expf(lrelu(asi.y + ad.y));
    float p2 = __expf(lrelu(asi.z + ad.z));
    float p3 = __expf(lrelu(asi.w + ad.w));
    float d0 = p0, d1 = p1, d2 = p2, d3 = p3;
    float a0 = p0 * xv.x, a1 = p1 * xv.y, a2 = p2 * xv.z, a3 = p3 * xv.w;

    for (int cs = beg; cs < end; cs += 32) {
        int cnt = min(32, end - cs);
        int j = cs + lane;
        if (lane < cnt) {
            int s = __ldg(&g_csr[j]);
            float4 a4 = *(const float4*)&g_as[s * 4];
            float4 q;
            q.x = __expf(lrelu(a4.x + ad.x));
            q.y = __expf(lrelu(a4.y + ad.y));
            q.z = __expf(lrelu(a4.z + ad.z));
            q.w = __expf(lrelu(a4.w + ad.w));
            ss[w][lane] = s;
            sq[w][lane] = q;
        }
        __syncwarp();
        #pragma unroll 4
        for (int t = 0; t < cnt; t++) {
            int st = ss[w][t];
            float4 qt = sq[w][t];
            float4 x4 = ldxw_h((long)st * 128, lane);
            d0 += qt.x; a0 = fmaf(qt.x, x4.x, a0);
            d1 += qt.y; a1 = fmaf(qt.y, x4.y, a1);
            d2 += qt.z; a2 = fmaf(qt.z, x4.z, a2);
            d3 += qt.w; a3 = fmaf(qt.w, x4.w, a3);
        }
        __syncwarp();
    }

    float r0 = a0 / (d0 + 1e-16f);
    float r1 = a1 / (d1 + 1e-16f);
    float r2 = a2 / (d2 + 1e-16f);
    float r3 = a3 / (d3 + 1e-16f);

    out[ob +  0] = fmaxf(id0 + r0 + b0, 0.f);
    out[ob + 32] = fmaxf(id1 + r1 + b1, 0.f);
    out[ob + 64] = fmaxf(id2 + r2 + b2, 0.f);
    out[ob + 96] = fmaxf(id3 + r3 + b3, 0.f);
}

// ---------------- launch ----------------
extern "C" void kernel_launch(void* const* d_in, const int* in_sizes, int n_in,
                              void* d_out, int out_size)
{
    const float* x        = (const float*)d_in[0];
    const int*   ei       = (const int*)d_in[1];
    const float* gamma    = (const float*)d_in[2];
    const float* beta     = (const float*)d_in[3];
    const float* Wgat     = (const float*)d_in[4];
    const float* att_src  = (const float*)d_in[5];
    const float* att_dst  = (const float*)d_in[6];
    const float* bias_gat = (const float*)d_in[7];
    const float* Wproj    = (const float*)d_in[8];
    const float* bproj    = (const float*)d_in[9];

    int n = in_sizes[0] / 128;
    int e = in_sizes[1] / 2;
    const int* src = ei;
    const int* dst = ei + e;
    int nb = (n + SCB - 1) / SCB;

    cudaFuncSetAttribute(node_k, cudaFuncAttributeMaxDynamicSharedMemorySize, NODE2_BYTES);

    cudaStream_t s2;
    cudaStreamCreate(&s2);
    cudaEvent_t evFork, evJoin;
    cudaEventCreateWithFlags(&evFork, cudaEventDisableTiming);
    cudaEventCreateWithFlags(&evJoin, cudaEventDisableTiming);

    cudaEventRecord(evFork, 0);
    cudaStreamWaitEvent(s2, evFork, 0);

    // side stream: CSR build (g_cur zeroed by gather_k of previous replay;
    // zero-initialized at module load for the very first run)
    hist_k<<<(e + 255) / 256, 256, 0, s2>>>(dst, e);
    scan1_k<<<nb, 256, 0, s2>>>(n);
    scat_k<<<(e + 255) / 256, 256, 0, s2>>>(src, dst, e);
    cudaEventRecord(evJoin, s2);

    // main stream: GEMM path
    prep2_k<<<256, 128>>>(gamma, beta, Wgat, Wproj);
    node_k<<<(n + TMM - 1) / TMM, 256, NODE2_BYTES>>>(x, att_src, att_dst, bproj, n);

    cudaStreamWaitEvent(0, evJoin, 0);
    gather_k<<<(n + 7) / 8, 256>>>(bias_gat, (float*)d_out, n);

    cudaEventDestroy(evFork);
    cudaEventDestroy(evJoin);
    cudaStreamDestroy(s2);
}

// round 17
// speedup vs baseline: 1.3799x; 1.1282x over previous
#include <cuda_runtime.h>
#include <cuda_bf16.h>
#include <cuda_fp16.h>

// Problem constants (fixed-shape problem)
#define MAXN 50176
#define MAXE 800256

// ---------------- scratch ----------------
__device__ __align__(16) __half g_xwh[MAXN * 128]; // xw per node (fp16), layout [node][cc*4+h]
__device__ __align__(16) __half g_idh[MAXN * 128]; // identity (fp16), layout [node][c]
__device__ __align__(16) float g_as[MAXN * 4];
__device__ __align__(16) float g_ad[MAXN * 4];
__device__ __align__(16) int   g_cur[MAXN];
__device__ int   g_off[MAXN + 1];
__device__ int   g_csr[MAXE];
__device__ volatile unsigned long long g_spack[64]; // packed (flag<<32 | aggregate)
__device__ float g_G[128];                          // colsum of fp16(gamma*W_gat)
__device__ float g_B[128];                          // beta @ W_gat
__device__ __align__(16) __half g_Bph[256 * 128];   // fp16 fused weights, PERMUTED frag layout [c][p]

// ---------------- mma helpers ----------------
// fp16 m16n8k16: a0=rowg klo, a1=rowg+8 klo, a2=rowg khi, a3=rowg+8 khi; b0=klo, b1=khi
__device__ __forceinline__ void mma16816(float* c, unsigned a0, unsigned a1, unsigned a2,
                                         unsigned a3, unsigned b0, unsigned b1) {
    asm volatile("mma.sync.aligned.m16n8k16.row.col.f32.f16.f16.f32 "
        "{%0,%1,%2,%3},{%4,%5,%6,%7},{%8,%9},{%0,%1,%2,%3};"
        : "+f"(c[0]), "+f"(c[1]), "+f"(c[2]), "+f"(c[3])
        : "r"(a0), "r"(a1), "r"(a2), "r"(a3), "r"(b0), "r"(b1));
}
__device__ __forceinline__ void cpa16(unsigned s, const void* g) {
    asm volatile("cp.async.ca.shared.global [%0], [%1], 16;" :: "r"(s), "l"(g));
}

// Fragment permutation: p = sp*32 + tig*8 + u*4 + grp*2 + h,
// logical k = (sp*2+u)*16 + grp*8 + tig*2 + h.
__device__ __forceinline__ int k_of_p(int p) {
    int sp = p >> 5, w5 = p & 31;
    int tig = w5 >> 3, w3 = w5 & 7;
    int u = w3 >> 2, grp = (w3 >> 1) & 1, h = w3 & 1;
    return (sp * 2 + u) * 16 + grp * 8 + tig * 2 + h;
}

// ---------------- prep: fp16 permuted weights + G/B colsums ----------------
// grid 256 (col c), block 128 (slot p).
__global__ void prep2_k(const float* __restrict__ gamma, const float* __restrict__ beta,
                        const float* __restrict__ Wgat, const float* __restrict__ Wproj) {
    __shared__ float s1[4], s2[4];
    int c = blockIdx.x, p = threadIdx.x;
    int lane = p & 31, wid = p >> 5;
    int k = k_of_p(p);
    float w;
    if (c < 128) w = gamma[k] * Wgat[k * 128 + c];
    else         w = Wproj[k * 128 + (c - 128)];
    __half wh = __float2half_rn(w);
    g_Bph[c * 128 + p] = wh;
    if (c < 128) {
        float sw = __half2float(wh);
        float sb = beta[k] * Wgat[k * 128 + c];
        #pragma unroll
        for (int o = 16; o > 0; o >>= 1) {
            sw += __shfl_xor_sync(0xFFFFFFFFu, sw, o);
            sb += __shfl_xor_sync(0xFFFFFFFFu, sb, o);
        }
        if (lane == 0) { s1[wid] = sw; s2[wid] = sb; }
        __syncthreads();
        if (p == 0) {
            g_G[c] = s1[0] + s1[1] + s1[2] + s1[3];
            g_B[c] = s2[0] + s2[1] + s2[2] + s2[3];
        }
    }
}

// ---------------- CSR build ----------------
__global__ void hist_k(const int* __restrict__ dst, int e) {
    if (blockIdx.x == 0 && threadIdx.x < 64) g_spack[threadIdx.x] = 0ull;
    int i = blockIdx.x * blockDim.x + threadIdx.x;
    if (i < e) atomicAdd(&g_cur[dst[i]], 1);
}

#define SCB 1024
__global__ void scan1_k(int n) {
    __shared__ int wsum[8];
    __shared__ int s_off;
    int b = blockIdx.x, tid = threadIdx.x, lane = tid & 31, wid = tid >> 5;
    int base = b * SCB + tid * 4;
    int4 v = make_int4(0, 0, 0, 0);
    if (base + 3 < n)      v = *(const int4*)&g_cur[base];
    else {
        if (base     < n) v.x = g_cur[base];
        if (base + 1 < n) v.y = g_cur[base + 1];
        if (base + 2 < n) v.z = g_cur[base + 2];
    }
    int tsum = v.x + v.y + v.z + v.w;
    int inc = tsum;
    #pragma unroll
    for (int o = 1; o < 32; o <<= 1) {
        int t = __shfl_up_sync(0xFFFFFFFFu, inc, o);
        if (lane >= o) inc += t;
    }
    if (lane == 31) wsum[wid] = inc;
    __syncthreads();

    if (tid == 0) {
        int tot = wsum[0] + wsum[1] + wsum[2] + wsum[3]
                + wsum[4] + wsum[5] + wsum[6] + wsum[7];
        g_spack[b] = (1ull << 32) | (unsigned)tot;
    }
    if (wid == 0 && lane < 8) {
        int wv = wsum[lane];
        int wi = wv;
        #pragma unroll
        for (int o = 1; o < 8; o <<= 1) {
            int t = __shfl_up_sync(0xFFu, wi, o);
            if (lane >= o) wi += t;
        }
        wsum[lane] = wi - wv;
    }
    if (wid == 1) {
        int acc = 0;
        for (int p = lane; p < b; p += 32) {
            unsigned long long pk;
            do { pk = g_spack[p]; } while (pk == 0ull);
            acc += (int)(unsigned)pk;
        }
        #pragma unroll
        for (int o = 16; o > 0; o >>= 1) acc += __shfl_xor_sync(0xFFFFFFFFu, acc, o);
        if (lane == 0) s_off = acc;
    }
    __syncthreads();

    int e0 = inc - tsum + wsum[wid] + s_off;
    int e1 = e0 + v.x, e2 = e1 + v.y, e3 = e2 + v.z, e4 = e3 + v.w;
    if (base     < n) { g_cur[base]     = e0; g_off[base + 1] = e1; }
    if (base + 1 < n) { g_cur[base + 1] = e1; g_off[base + 2] = e2; }
    if (base + 2 < n) { g_cur[base + 2] = e2; g_off[base + 3] = e3; }
    if (base + 3 < n) { g_cur[base + 3] = e3; g_off[base + 4] = e4; }
    if (b == 0 && tid == 0) g_off[0] = 0;
}

__global__ void scat_k(const int* __restrict__ src, const int* __restrict__ dst, int e) {
    int i = blockIdx.x * blockDim.x + threadIdx.x;
    if (i < e) {
        int p = atomicAdd(&g_cur[dst[i]], 1);
        g_csr[p] = src[i];
    }
}

// ---------------- node kernel: LN + dual GEMM (fp16 m16n8k16) + attn dots ----------------
// TMM=64 rows/block; full B resident in smem (no pipeline loop).
#define TMM 64
#define PA 160                               // A pitch in halves (320B; conflict-mitigating)
#define PB 160                               // B pitch in halves
#define SMH_A 0
#define SMH_B (TMM * PA)                     // 10240 halves
#define SMH_FLOATS (SMH_B + 256 * PB)        // 51200 halves -> byte 102400
#define FS_MU 0
#define FS_RS 64
#define FS_ATT 128
#define FS_G 384
#define FS_BB 512
#define FS_BP 640
#define NODE2_BYTES (SMH_FLOATS * 2 + 768 * 4)   // 105472 B

__global__ void __launch_bounds__(256, 2) node_k(
    const float* __restrict__ x, const float* __restrict__ att_src,
    const float* __restrict__ att_dst, const float* __restrict__ bproj, int n)
{
    extern __shared__ __align__(16) char smraw[];
    __half* Ah = (__half*)smraw;
    char* Bb = smraw + SMH_B * 2;            // B base (bytes)
    float* fs = (float*)(smraw + SMH_FLOATS * 2);

    int tid = threadIdx.x;
    int wid = tid >> 5, lane = tid & 31;
    int g = lane >> 2, tig = lane & 3;
    int i0 = blockIdx.x * TMM;
    unsigned smbase = (unsigned)__cvta_generic_to_shared(smraw);

    // start B load first (cp.async): 256 cols x 256 bytes = 4096 x 16B chunks
    {
        unsigned bs = smbase + SMH_B * 2;
        #pragma unroll
        for (int u = 0; u < 16; u++) {
            int idx = u * 256 + tid;          // 0..4095
            int c = idx >> 4, q = idx & 15;   // q: 8-half (16B) group within col
            cpa16(bs + c * (PB * 2) + q * 16, g_Bph + c * 128 + q * 8);
        }
        asm volatile("cp.async.commit_group;");
    }

    if (tid < 128) {
        fs[FS_ATT + tid]       = att_src[tid];
        fs[FS_ATT + 128 + tid] = att_dst[tid];
        fs[FS_G + tid]  = g_G[tid];
        fs[FS_BB + tid] = g_B[tid];
        fs[FS_BP + tid] = bproj[tid];
    }

    // A fill (fp16, permuted frag layout) + LayerNorm stats
    for (int rr = 0; rr < 8; rr++) {
        int r = wid * 8 + rr;
        int node = i0 + r;
        float4 v = make_float4(0.f, 0.f, 0.f, 0.f);
        if (node < n) v = *(const float4*)&x[(long)node * 128 + lane * 4];
        float s = v.x + v.y + v.z + v.w;
        float q = v.x * v.x + v.y * v.y + v.z * v.z + v.w * v.w;
        #pragma unroll
        for (int o = 16; o > 0; o >>= 1) {
            s += __shfl_xor_sync(0xFFFFFFFFu, s, o);
            q += __shfl_xor_sync(0xFFFFFFFFu, q, o);
        }
        float mu = s * (1.f / 128.f);
        float var = q * (1.f / 128.f) - mu * mu;
        if (lane == 0) { fs[FS_MU + r] = mu; fs[FS_RS + r] = rsqrtf(var + 1e-5f); }
        // lane holds logical k = lane*4 .. +3; pairs land at p1 and p1+8
        int k0 = lane * 4;
        int sK = k0 >> 4, rem = k0 & 15;
        int grp = rem >> 3, rem2 = rem & 7;
        int tig0 = rem2 >> 1;
        int spK = sK >> 1, uK = sK & 1;
        int p1 = spK * 32 + tig0 * 8 + uK * 4 + grp * 2;
        *(__half2*)&Ah[r * PA + p1]     = __floats2half2_rn(v.x, v.y);
        *(__half2*)&Ah[r * PA + p1 + 8] = __floats2half2_rn(v.z, v.w);
    }

    asm volatile("cp.async.wait_group 0;");
    __syncthreads();

    float c[4][4][4];
    #pragma unroll
    for (int a = 0; a < 4; a++)
        #pragma unroll
        for (int b = 0; b < 4; b++)
            #pragma unroll
            for (int d = 0; d < 4; d++) c[a][b][d] = 0.f;

    int colb = wid * 32;

    #pragma unroll
    for (int sp = 0; sp < 4; sp++) {
        uint4 bv[4];
        #pragma unroll
        for (int ni = 0; ni < 4; ni++) {
            int col = colb + ni * 8 + g;
            bv[ni] = *(const uint4*)(Bb + col * (PB * 2) + sp * 64 + tig * 16);
        }
        #pragma unroll
        for (int mi = 0; mi < 4; mi++) {
            const char* Ab = smraw;
            uint4 ug  = *(const uint4*)(Ab + (mi * 16 + g) * (PA * 2) + sp * 64 + tig * 16);
            uint4 ug8 = *(const uint4*)(Ab + (mi * 16 + g + 8) * (PA * 2) + sp * 64 + tig * 16);
            #pragma unroll
            for (int ni = 0; ni < 4; ni++) {
                mma16816(c[mi][ni], ug.x, ug8.x, ug.y, ug8.y, bv[ni].x, bv[ni].y);
                mma16816(c[mi][ni], ug.z, ug8.z, ug.w, ug8.w, bv[ni].z, bv[ni].w);
            }
        }
    }

    // Epilogue
    if (wid < 4) {
        int h = wid;
        #pragma unroll
        for (int mi = 0; mi < 4; mi++) {
            #pragma unroll
            for (int hf = 0; hf < 2; hf++) {
                int r = mi * 16 + g + hf * 8;
                int node = i0 + r;
                float mu = fs[FS_MU + r], rs = fs[FS_RS + r];
                float ps = 0.f, pd = 0.f;
                #pragma unroll
                for (int ni = 0; ni < 4; ni++) {
                    #pragma unroll
                    for (int j = 0; j < 2; j++) {
                        int cl = ni * 8 + 2 * tig + j;
                        int cg = colb + cl;
                        float acc = c[mi][ni][hf * 2 + j];
                        float val = rs * (acc - mu * fs[FS_G + cg]) + fs[FS_BB + cg];
                        ps += val * fs[FS_ATT + cg];
                        pd += val * fs[FS_ATT + 128 + cg];
                        if (node < n)
                            g_xwh[(long)node * 128 + cl * 4 + h] = __float2half_rn(val);
                    }
                }
                ps += __shfl_xor_sync(0xFFFFFFFFu, ps, 1);
                ps += __shfl_xor_sync(0xFFFFFFFFu, ps, 2);
                pd += __shfl_xor_sync(0xFFFFFFFFu, pd, 1);
                pd += __shfl_xor_sync(0xFFFFFFFFu, pd, 2);
                if (tig == 0 && node < n) {
                    g_as[node * 4 + h] = ps;
                    g_ad[node * 4 + h] = pd;
                }
            }
        }
    } else {
        #pragma unroll
        for (int mi = 0; mi < 4; mi++) {
            #pragma unroll
            for (int hf = 0; hf < 2; hf++) {
                int r = mi * 16 + g + hf * 8;
                int node = i0 + r;
                if (node >= n) continue;
                #pragma unroll
                for (int ni = 0; ni < 4; ni++) {
                    int cid0 = (wid - 4) * 32 + ni * 8 + 2 * tig;
                    float v0 = c[mi][ni][hf * 2 + 0] + fs[FS_BP + cid0];
                    float v1 = c[mi][ni][hf * 2 + 1] + fs[FS_BP + cid0 + 1];
                    *(__half2*)&g_idh[(long)node * 128 + cid0] = __floats2half2_rn(v0, v1);
                }
            }
        }
    }
}

// ---------------- gather: 1 warp per node (R11 form, exact) ----------------
__device__ __forceinline__ float lrelu(float z) { return z > 0.f ? z : 0.2f * z; }

__device__ __forceinline__ float4 ldxw_h(long idx128, int lane) {
    const __half* p = g_xwh + idx128 + lane * 4;
    uint2 u = *(const uint2*)p;
    __half2 h0 = *reinterpret_cast<__half2*>(&u.x);
    __half2 h1 = *reinterpret_cast<__half2*>(&u.y);
    float2 f0 = __half22float2(h0);
    float2 f1 = __half22float2(h1);
    return make_float4(f0.x, f0.y, f1.x, f1.y);
}

__global__ void __launch_bounds__(256) gather_k(const float* __restrict__ bias,
                                                float* __restrict__ out, int n)
{
    __shared__ float4 sq[8][32];
    __shared__ int    ss[8][32];
    int w = threadIdx.x >> 5;
    int lane = threadIdx.x & 31;
    int i = (blockIdx.x * 256 + threadIdx.x) >> 5;
    if (i >= n) return;

    float4 ad  = *(const float4*)&g_ad[i * 4];
    float4 asi = *(const float4*)&g_as[i * 4];
    int beg = g_off[i], end = g_off[i + 1];
    long myb = (long)i * 128;
    float4 xv = ldxw_h(myb, lane);

    float p0 = __expf(lrelu(asi.x + ad.x));
    float p1 = __expf(lrelu(asi.y + ad.y));
    float p2 = __expf(lrelu(asi.z + ad.z));
    float p3 = __expf(lrelu(asi.w + ad.w));
    float d0 = p0, d1 = p1, d2 = p2, d3 = p3;
    float a0 = p0 * xv.x, a1 = p1 * xv.y, a2 = p2 * xv.z, a3 = p3 * xv.w;

    for (int cs = beg; cs < end; cs += 32) {
        int cnt = min(32, end - cs);
        int j = cs + lane;
        if (lane < cnt) {
            int s = __ldg(&g_csr[j]);
            float4 a4 = *(const float4*)&g_as[s * 4];
            float4 q;
            q.x = __expf(lrelu(a4.x + ad.x));
            q.y = __expf(lrelu(a4.y + ad.y));
            q.z = __expf(lrelu(a4.z + ad.z));
            q.w = __expf(lrelu(a4.w + ad.w));
            ss[w][lane] = s;
            sq[w][lane] = q;
        }
        __syncwarp();
        #pragma unroll 4
        for (int t = 0; t < cnt; t++) {
            int st = ss[w][t];
            float4 qt = sq[w][t];
            float4 x4 = ldxw_h((long)st * 128, lane);
            d0 += qt.x; a0 = fmaf(qt.x, x4.x, a0);
            d1 += qt.y; a1 = fmaf(qt.y, x4.y, a1);
            d2 += qt.z; a2 = fmaf(qt.z, x4.z, a2);
            d3 += qt.w; a3 = fmaf(qt.w, x4.w, a3);
        }
        __syncwarp();
    }

    float r0 = a0 / (d0 + 1e-16f);
    float r1 = a1 / (d1 + 1e-16f);
    float r2 = a2 / (d2 + 1e-16f);
    float r3 = a3 / (d3 + 1e-16f);

    long ob = myb + lane;
    out[ob +  0] = fmaxf(__half2float(g_idh[ob +  0]) + r0 + __ldg(&bias[lane +  0]), 0.f);
    out[ob + 32] = fmaxf(__half2float(g_idh[ob + 32]) + r1 + __ldg(&bias[lane + 32]), 0.f);
    out[ob + 64] = fmaxf(__half2float(g_idh[ob + 64]) + r2 + __ldg(&bias[lane + 64]), 0.f);
    out[ob + 96] = fmaxf(__half2float(g_idh[ob + 96]) + r3 + __ldg(&bias[lane + 96]), 0.f);
}

// ---------------- launch ----------------
extern "C" void kernel_launch(void* const* d_in, const int* in_sizes, int n_in,
                              void* d_out, int out_size)
{
    const float* x        = (const float*)d_in[0];
    const int*   ei       = (const int*)d_in[1];
    const float* gamma    = (const float*)d_in[2];
    const float* beta     = (const float*)d_in[3];
    const float* Wgat     = (const float*)d_in[4];
    const float* att_src  = (const float*)d_in[5];
    const float* att_dst  = (const float*)d_in[6];
    const float* bias_gat = (const float*)d_in[7];
    const float* Wproj    = (const float*)d_in[8];
    const float* bproj    = (const float*)d_in[9];

    int n = in_sizes[0] / 128;
    int e = in_sizes[1] / 2;
    const int* src = ei;
    const int* dst = ei + e;
    int nb = (n + SCB - 1) / SCB;

    void* curp = nullptr;
    cudaGetSymbolAddress(&curp, g_cur);

    cudaFuncSetAttribute(node_k, cudaFuncAttributeMaxDynamicSharedMemorySize, NODE2_BYTES);

    cudaStream_t s2;
    cudaStreamCreate(&s2);
    cudaEvent_t evFork, evJoin;
    cudaEventCreateWithFlags(&evFork, cudaEventDisableTiming);
    cudaEventCreateWithFlags(&evJoin, cudaEventDisableTiming);

    cudaEventRecord(evFork, 0);
    cudaStreamWaitEvent(s2, evFork, 0);

    // side stream: CSR build
    cudaMemsetAsync(curp, 0, n * sizeof(int), s2);
    hist_k<<<(e + 255) / 256, 256, 0, s2>>>(dst, e);
    scan1_k<<<nb, 256, 0, s2>>>(n);
    scat_k<<<(e + 255) / 256, 256, 0, s2>>>(src, dst, e);
    cudaEventRecord(evJoin, s2);

    // main stream: GEMM path
    prep2_k<<<256, 128>>>(gamma, beta, Wgat, Wproj);
    node_k<<<(n + TMM - 1) / TMM, 256, NODE2_BYTES>>>(x, att_src, att_dst, bproj, n);

    cudaStreamWaitEvent(0, evJoin, 0);
    gather_k<<<(n + 7) / 8, 256>>>(bias_gat, (float*)d_out, n);

    cudaEventDestroy(evFork);
    cudaEventDestroy(evJoin);
    cudaStreamDestroy(s2);
}